// round 13
// baseline (speedup 1.0000x reference)
#include <cuda_runtime.h>
#include <cuda_fp16.h>
#include <cstdint>

#define MAX_N 50000
#define MAX_E 800000
#define D 128
#define SCAN_B 512
#define MAX_BLK 128   // >= ceil(MAX_N/SCAN_B)

// Scratch (device globals: allocation forbidden in kernel_launch)
__device__ int    g_mode;             // 1 = edge_index is int64, 0 = int32
__device__ int    g_deg[MAX_N];       // edge in-degree (excl self-loop)
__device__ int    g_off[MAX_N];       // CSR row offsets
__device__ int    g_cur[MAX_N];       // fill cursors
__device__ int    g_bsum[MAX_BLK];    // scan block sums
__device__ int    g_scan_ctr;         // last-block ticket (zero-init, self-reset)
__device__ float  g_dis[MAX_N];       // rsqrt(deg+1)
__device__ int    g_src[MAX_E];       // CSR column indices (source nodes)
__device__ __half g_h[4ull * MAX_N * D];  // h = x @ W^T in fp16, per set

// ---------------------------------------------------------------------------
__global__ void k_detect_zero(const void* ei, int E, int N) {
    int i = blockIdx.x * blockDim.x + threadIdx.x;
    if (i < N) g_deg[i] = 0;
    if (i == 0) {
        const long long* p64 = (const long long*)ei;
        int n = E < 32 ? E : 32;
        int ok64 = 1;
        for (int k = 0; k < n; k++) {
            long long v = p64[k];
            if (v < 0 || v >= (long long)N) { ok64 = 0; break; }
        }
        g_mode = ok64;
    }
}

__device__ __forceinline__ int edge_at(const void* ei, long long idx, int mode) {
    if (mode) return (int)((const long long*)ei)[idx];
    return ((const int*)ei)[idx];
}

__global__ void k_count(const void* __restrict__ ei, int E, int N) {
    int e = blockIdx.x * blockDim.x + threadIdx.x;
    if (e >= E) return;
    int mode = g_mode;
    int d = edge_at(ei, (long long)E + e, mode);
    if (d >= 0 && d < N) atomicAdd(&g_deg[d], 1);
}

// per-block exclusive scan; last-arriving block scans the block sums in place
__global__ void k_scan_block(int N, int nb) {
    __shared__ int sm[SCAN_B];
    int i = blockIdx.x * SCAN_B + threadIdx.x;
    int v = (i < N) ? g_deg[i] : 0;
    sm[threadIdx.x] = v;
    __syncthreads();
#pragma unroll
    for (int o = 1; o < SCAN_B; o <<= 1) {
        int t = (threadIdx.x >= o) ? sm[threadIdx.x - o] : 0;
        __syncthreads();
        sm[threadIdx.x] += t;
        __syncthreads();
    }
    if (i < N) g_off[i] = sm[threadIdx.x] - v;   // exclusive (local)
    if (threadIdx.x == SCAN_B - 1) g_bsum[blockIdx.x] = sm[SCAN_B - 1];
    __syncthreads();
    if (threadIdx.x == 0) {
        __threadfence();
        int t = atomicAdd(&g_scan_ctr, 1);
        if (t == nb - 1) {
            g_scan_ctr = 0;
            __threadfence();
            int acc = 0;
            for (int b = 0; b < nb; b++) { int s = g_bsum[b]; g_bsum[b] = acc; acc += s; }
        }
    }
}

__global__ void k_finalize(int N) {
    int i = blockIdx.x * blockDim.x + threadIdx.x;
    if (i < N) {
        int o = g_off[i] + g_bsum[i / SCAN_B];
        g_off[i] = o;
        g_cur[i] = o;
        g_dis[i] = rsqrtf((float)(g_deg[i] + 1));
    }
}

__global__ void k_fill(const void* __restrict__ ei, int E, int N) {
    int e = blockIdx.x * blockDim.x + threadIdx.x;
    if (e >= E) return;
    int mode = g_mode;
    int s = edge_at(ei, e, mode);
    int d = edge_at(ei, (long long)E + e, mode);
    if (s >= 0 && s < N && d >= 0 && d < N) {
        int pos = atomicAdd(&g_cur[d], 1);
        if (pos >= 0 && pos < E) g_src[pos] = s;
    }
}

// ---------------------------------------------------------------------------
// GEMM (no bias): g_h[set] = fp16( x_set @ W^T )   (fp16 HMMA m16n8k16, f32 acc)
// Block 128(M)x128(N), 8 warps 2(M)x4(N). grid.y = weight pair (2 sets/block).
// W fp16 staged once; full fp32 x tile staged via cp.async; 2 syncs per set;
// mainloop has ZERO syncs. __launch_bounds__(256,2) + 204 KB smem across 2 CTAs.
#define GP 68    // W pitch (half2 units): 4g+c distinct mod 32
#define XPF 136  // x pitch (floats): per-half-warp 8g+2c distinct mod 32 (LDS.64)

__device__ __forceinline__ uint32_t pack_h2(float lo, float hi) {
    __half2 h = __floats2half2_rn(lo, hi);
    return *(uint32_t*)&h;
}

__device__ __forceinline__ void mma_f16(float* d, const uint32_t* a, const uint32_t* b) {
    asm volatile(
        "mma.sync.aligned.m16n8k16.row.col.f32.f16.f16.f32 "
        "{%0,%1,%2,%3}, {%4,%5,%6,%7}, {%8,%9}, {%0,%1,%2,%3};"
        : "+f"(d[0]), "+f"(d[1]), "+f"(d[2]), "+f"(d[3])
        : "r"(a[0]), "r"(a[1]), "r"(a[2]), "r"(a[3]), "r"(b[0]), "r"(b[1]));
}

__device__ __forceinline__ void cp16(uint32_t smem_dst, const void* gsrc, int bytes) {
    asm volatile("cp.async.cg.shared.global [%0], [%1], 16, %2;"
                 :: "r"(smem_dst), "l"(gsrc), "r"(bytes));
}

__global__ void __launch_bounds__(256, 2) k_gemm(
        const float* __restrict__ x0, const float* __restrict__ x1,
        const float* __restrict__ x2, const float* __restrict__ x3,
        const float* __restrict__ W1, const float* __restrict__ W2,
        int N) {
    extern __shared__ float smem[];
    uint32_t* Wh = (uint32_t*)smem;            // [128][GP] half2
    float*    Xs = smem + 128 * GP;            // [128][XPF] fp32

    int p = blockIdx.y;                        // 0 -> W1 (sets 0,2), 1 -> W2 (sets 1,3)
    const float* Wp = p ? W2 : W1;

    int tid = threadIdx.x;
    int m0 = blockIdx.x * 128;
    int warp = tid >> 5, lane = tid & 31;
    int wm = warp >> 2, wn = warp & 3;
    int g = lane >> 2, c = lane & 3;

    uint32_t xs_base = (uint32_t)__cvta_generic_to_shared(Xs);

    // stage full W once (through regs: needs fp32->fp16 conversion)
    for (int idx = tid; idx < 128 * 32; idx += 256) {
        int n = idx >> 5, q4 = idx & 31;
        float4 v = *(const float4*)&Wp[n * D + q4 * 4];
        Wh[n * GP + q4 * 2]     = pack_h2(v.x, v.y);
        Wh[n * GP + q4 * 2 + 1] = pack_h2(v.z, v.w);
    }

    for (int ss = 0; ss < 2; ss++) {
        int set = p + ss * 2;
        const float* xp = (set == 0) ? x0 : (set == 1) ? x1 : (set == 2) ? x2 : x3;
        __half* h = g_h + (size_t)set * N * D;

        // stage full fp32 x tile via cp.async: 4096 x 16B, 16 per thread
        for (int idx = tid; idx < 128 * 32; idx += 256) {
            int row = idx >> 5, q4 = idx & 31;
            int gm = m0 + row;
            uint32_t dst = xs_base + (row * XPF + q4 * 4) * 4;
            const void* src = &xp[(size_t)(gm < N ? gm : 0) * D + q4 * 4];
            cp16(dst, src, (gm < N) ? 16 : 0);
        }
        asm volatile("cp.async.commit_group;");
        asm volatile("cp.async.wait_group 0;");
        __syncthreads();

        float acc[4][4][4];
#pragma unroll
        for (int mi = 0; mi < 4; mi++)
#pragma unroll
            for (int ni = 0; ni < 4; ni++)
#pragma unroll
                for (int r = 0; r < 4; r++) acc[mi][ni][r] = 0.0f;

#pragma unroll
        for (int ks = 0; ks < 8; ks++) {
            int kk = ks * 16;                 // float offset of this k-step
            uint32_t a[4][4], b[4][2];
#pragma unroll
            for (int mi = 0; mi < 4; mi++) {
                int r = wm * 64 + mi * 16 + g;
                float2 f0 = *(const float2*)&Xs[r * XPF + kk + c * 2];
                float2 f1 = *(const float2*)&Xs[(r + 8) * XPF + kk + c * 2];
                float2 f2 = *(const float2*)&Xs[r * XPF + kk + 8 + c * 2];
                float2 f3 = *(const float2*)&Xs[(r + 8) * XPF + kk + 8 + c * 2];
                a[mi][0] = pack_h2(f0.x, f0.y);
                a[mi][1] = pack_h2(f1.x, f1.y);
                a[mi][2] = pack_h2(f2.x, f2.y);
                a[mi][3] = pack_h2(f3.x, f3.y);
            }
#pragma unroll
            for (int ni = 0; ni < 4; ni++) {
                int n = wn * 32 + ni * 8 + g;
                b[ni][0] = Wh[n * GP + ks * 8 + c];
                b[ni][1] = Wh[n * GP + ks * 8 + c + 4];
            }
#pragma unroll
            for (int mi = 0; mi < 4; mi++)
#pragma unroll
                for (int ni = 0; ni < 4; ni++)
                    mma_f16(acc[mi][ni], a[mi], b[ni]);
        }

        // epilogue: convert to fp16, write half2 per fragment pair
#pragma unroll
        for (int ni = 0; ni < 4; ni++) {
            int cb = wn * 32 + ni * 8 + 2 * c;
#pragma unroll
            for (int mi = 0; mi < 4; mi++) {
                int r0 = m0 + wm * 64 + mi * 16 + g;
                int r1 = r0 + 8;
                if (r0 < N)
                    *(__half2*)&h[(size_t)r0 * D + cb] =
                        __floats2half2_rn(acc[mi][ni][0], acc[mi][ni][1]);
                if (r1 < N)
                    *(__half2*)&h[(size_t)r1 * D + cb] =
                        __floats2half2_rn(acc[mi][ni][2], acc[mi][ni][3]);
            }
        }
        __syncthreads();   // protect Xs before next set restages
    }
}

// ---------------------------------------------------------------------------
// Aggregation: out_s[i] = sum_j norm_ij * h_s[j]  + b_s   (fp32 accumulate)
__global__ void k_agg(const float* __restrict__ b1, const float* __restrict__ b2,
                      float* __restrict__ out, int N) {
    int gt = blockIdx.x * blockDim.x + threadIdx.x;
    int i = gt >> 5;
    int lane = gt & 31;
    if (i >= N) return;

    int pair = lane >> 4;
    int cp = lane & 15;
    int setA = pair * 2;
    int setB = setA + 1;

    const uint4* HA = (const uint4*)(g_h + (size_t)setA * N * D);
    const uint4* HB = (const uint4*)(g_h + (size_t)setB * N * D);

    float di = g_dis[i];
    float d2 = di * di;

    float accA[8], accB[8];
    {
        uint4 ua = HA[(size_t)i * 16 + cp];
        uint4 ub = HB[(size_t)i * 16 + cp];
        const half2* pa = (const half2*)&ua;
        const half2* pb = (const half2*)&ub;
#pragma unroll
        for (int q = 0; q < 4; q++) {
            float2 fa = __half22float2(pa[q]);
            float2 fb = __half22float2(pb[q]);
            accA[2 * q] = fa.x * d2; accA[2 * q + 1] = fa.y * d2;
            accB[2 * q] = fb.x * d2; accB[2 * q + 1] = fb.y * d2;
        }
    }

    int beg = g_off[i];
    int end = beg + g_deg[i];
    for (int j = beg; j < end; j++) {
        int s = g_src[j];
        float w = di * g_dis[s];
        uint4 ua = HA[(size_t)s * 16 + cp];
        uint4 ub = HB[(size_t)s * 16 + cp];
        const half2* pa = (const half2*)&ua;
        const half2* pb = (const half2*)&ub;
#pragma unroll
        for (int q = 0; q < 4; q++) {
            float2 fa = __half22float2(pa[q]);
            float2 fb = __half22float2(pb[q]);
            accA[2 * q]     = fmaf(fa.x, w, accA[2 * q]);
            accA[2 * q + 1] = fmaf(fa.y, w, accA[2 * q + 1]);
            accB[2 * q]     = fmaf(fb.x, w, accB[2 * q]);
            accB[2 * q + 1] = fmaf(fb.y, w, accB[2 * q + 1]);
        }
    }

    int col = cp * 8;
    float4 bA0 = *(const float4*)&b1[col];
    float4 bA1 = *(const float4*)&b1[col + 4];
    float4 bB0 = *(const float4*)&b2[col];
    float4 bB1 = *(const float4*)&b2[col + 4];

    float* oA = out + (size_t)setA * N * D + (size_t)i * D + col;
    float* oB = out + (size_t)setB * N * D + (size_t)i * D + col;
    *(float4*)oA       = make_float4(accA[0] + bA0.x, accA[1] + bA0.y,
                                     accA[2] + bA0.z, accA[3] + bA0.w);
    *(float4*)(oA + 4) = make_float4(accA[4] + bA1.x, accA[5] + bA1.y,
                                     accA[6] + bA1.z, accA[7] + bA1.w);
    *(float4*)oB       = make_float4(accB[0] + bB0.x, accB[1] + bB0.y,
                                     accB[2] + bB0.z, accB[3] + bB0.w);
    *(float4*)(oB + 4) = make_float4(accB[4] + bB1.x, accB[5] + bB1.y,
                                     accB[6] + bB1.z, accB[7] + bB1.w);
}

// ---------------------------------------------------------------------------
extern "C" void kernel_launch(void* const* d_in, const int* in_sizes, int n_in,
                              void* d_out, int out_size) {
    const float* x0 = (const float*)d_in[0];  // x_r1 (W1,b1)
    const float* x1 = (const float*)d_in[1];  // x_r2 (W2,b2)
    const float* x2 = (const float*)d_in[2];  // x_i1 (W1,b1)
    const float* x3 = (const float*)d_in[3];  // x_i2 (W2,b2)
    const void*  ei = d_in[4];                // edge_index: int64 OR int32
    const float* W1 = (const float*)d_in[5];
    const float* b1 = (const float*)d_in[6];
    const float* W2 = (const float*)d_in[7];
    const float* b2 = (const float*)d_in[8];
    float* out = (float*)d_out;

    int N = in_sizes[0] / D;
    int E = in_sizes[4] / 2;
    int nb_scan = (N + SCAN_B - 1) / SCAN_B;

    // dtype probe + zero + CSR build + normalization
    k_detect_zero<<<(N + 255) / 256, 256>>>(ei, E, N);
    k_count<<<(E + 255) / 256, 256>>>(ei, E, N);

    // GEMM (independent of CSR): h = fp16(x @ W^T), 2 sets per block
    {
        int smem = (128 * GP + 128 * XPF) * 4;   // 34816 + 69632 = 104448 B
        cudaFuncSetAttribute(k_gemm, cudaFuncAttributeMaxDynamicSharedMemorySize, smem);
        dim3 grid((N + 127) / 128, 2);
        k_gemm<<<grid, 256, smem>>>(x0, x1, x2, x3, W1, W2, N);
    }

    k_scan_block<<<nb_scan, SCAN_B>>>(N, nb_scan);
    k_finalize<<<(N + 255) / 256, 256>>>(N);
    k_fill<<<(E + 255) / 256, 256>>>(ei, E, N);

    // aggregate fp16 h with fp32 accumulation, add bias, write out
    {
        long long threads = (long long)N * 32;
        int blocks = (int)((threads + 255) / 256);
        k_agg<<<blocks, 256>>>(b1, b2, out, N);
    }
}

// round 14
// speedup vs baseline: 1.0835x; 1.0835x over previous
#include <cuda_runtime.h>
#include <cuda_fp16.h>
#include <cstdint>

#define MAX_N 50000
#define MAX_E 800000
#define D 128
#define SCAN_B 512
#define MAX_BLK 128   // >= ceil(MAX_N/SCAN_B)

// Scratch (device globals: allocation forbidden in kernel_launch)
__device__ int    g_mode;             // 1 = edge_index is int64, 0 = int32
__device__ int    g_deg[MAX_N];       // edge in-degree (excl self-loop)
__device__ int    g_off[MAX_N];       // CSR row offsets
__device__ int    g_cur[MAX_N];       // fill cursors
__device__ int    g_bsum[MAX_BLK];    // scan block sums
__device__ int    g_scan_ctr;         // last-block ticket (zero-init, self-reset)
__device__ float  g_dis[MAX_N];       // rsqrt(deg+1)
__device__ int    g_src[MAX_E];       // CSR column indices (source nodes)
__device__ __half g_h[4ull * MAX_N * D];  // h = x @ W^T in fp16, per set

// Fork-join resources, created once at module load (host-side only; no device mem)
struct StreamRes {
    cudaStream_t s2;
    cudaEvent_t  fork_ev, join_ev;
    StreamRes() {
        cudaStreamCreateWithFlags(&s2, cudaStreamNonBlocking);
        cudaEventCreateWithFlags(&fork_ev, cudaEventDisableTiming);
        cudaEventCreateWithFlags(&join_ev, cudaEventDisableTiming);
    }
};
static StreamRes g_res;

// ---------------------------------------------------------------------------
__global__ void k_detect_zero(const void* ei, int E, int N) {
    int i = blockIdx.x * blockDim.x + threadIdx.x;
    if (i < N) g_deg[i] = 0;
    if (i == 0) {
        const long long* p64 = (const long long*)ei;
        int n = E < 32 ? E : 32;
        int ok64 = 1;
        for (int k = 0; k < n; k++) {
            long long v = p64[k];
            if (v < 0 || v >= (long long)N) { ok64 = 0; break; }
        }
        g_mode = ok64;
    }
}

__device__ __forceinline__ int edge_at(const void* ei, long long idx, int mode) {
    if (mode) return (int)((const long long*)ei)[idx];
    return ((const int*)ei)[idx];
}

__global__ void k_count(const void* __restrict__ ei, int E, int N) {
    int e = blockIdx.x * blockDim.x + threadIdx.x;
    if (e >= E) return;
    int mode = g_mode;
    int d = edge_at(ei, (long long)E + e, mode);
    if (d >= 0 && d < N) atomicAdd(&g_deg[d], 1);
}

// per-block exclusive scan; last-arriving block scans the block sums in place
__global__ void k_scan_block(int N, int nb) {
    __shared__ int sm[SCAN_B];
    int i = blockIdx.x * SCAN_B + threadIdx.x;
    int v = (i < N) ? g_deg[i] : 0;
    sm[threadIdx.x] = v;
    __syncthreads();
#pragma unroll
    for (int o = 1; o < SCAN_B; o <<= 1) {
        int t = (threadIdx.x >= o) ? sm[threadIdx.x - o] : 0;
        __syncthreads();
        sm[threadIdx.x] += t;
        __syncthreads();
    }
    if (i < N) g_off[i] = sm[threadIdx.x] - v;   // exclusive (local)
    if (threadIdx.x == SCAN_B - 1) g_bsum[blockIdx.x] = sm[SCAN_B - 1];
    __syncthreads();
    if (threadIdx.x == 0) {
        __threadfence();
        int t = atomicAdd(&g_scan_ctr, 1);
        if (t == nb - 1) {
            g_scan_ctr = 0;
            __threadfence();
            int acc = 0;
            for (int b = 0; b < nb; b++) { int s = g_bsum[b]; g_bsum[b] = acc; acc += s; }
        }
    }
}

__global__ void k_finalize(int N) {
    int i = blockIdx.x * blockDim.x + threadIdx.x;
    if (i < N) {
        int o = g_off[i] + g_bsum[i / SCAN_B];
        g_off[i] = o;
        g_cur[i] = o;
        g_dis[i] = rsqrtf((float)(g_deg[i] + 1));
    }
}

__global__ void k_fill(const void* __restrict__ ei, int E, int N) {
    int e = blockIdx.x * blockDim.x + threadIdx.x;
    if (e >= E) return;
    int mode = g_mode;
    int s = edge_at(ei, e, mode);
    int d = edge_at(ei, (long long)E + e, mode);
    if (s >= 0 && s < N && d >= 0 && d < N) {
        int pos = atomicAdd(&g_cur[d], 1);
        if (pos >= 0 && pos < E) g_src[pos] = s;
    }
}

// ---------------------------------------------------------------------------
// GEMM (no bias): g_h[set] = fp16( x_set @ W^T )   (fp16 HMMA m16n8k16, f32 acc)
// Round-12 config: W staged once, x in K=32 double-buffered chunks, 2 sets/block.
#define GP 68   // W pitch (half2 units)
#define XP 20   // x chunk pitch (half2 units)
#define NCHUNK 4

__device__ __forceinline__ uint32_t pack_h2(float lo, float hi) {
    __half2 h = __floats2half2_rn(lo, hi);
    return *(uint32_t*)&h;
}

__device__ __forceinline__ void mma_f16(float* d, const uint32_t* a, const uint32_t* b) {
    asm volatile(
        "mma.sync.aligned.m16n8k16.row.col.f32.f16.f16.f32 "
        "{%0,%1,%2,%3}, {%4,%5,%6,%7}, {%8,%9}, {%0,%1,%2,%3};"
        : "+f"(d[0]), "+f"(d[1]), "+f"(d[2]), "+f"(d[3])
        : "r"(a[0]), "r"(a[1]), "r"(a[2]), "r"(a[3]), "r"(b[0]), "r"(b[1]));
}

__global__ void __launch_bounds__(256, 2) k_gemm(
        const float* __restrict__ x0, const float* __restrict__ x1,
        const float* __restrict__ x2, const float* __restrict__ x3,
        const float* __restrict__ W1, const float* __restrict__ W2,
        int N) {
    __shared__ uint32_t Wh[128][GP];
    __shared__ uint32_t Xh[2][128][XP];

    int p = blockIdx.y;
    const float* Wp = p ? W2 : W1;

    int tid = threadIdx.x;
    int m0 = blockIdx.x * 128;
    int warp = tid >> 5, lane = tid & 31;
    int wm = warp >> 2, wn = warp & 3;
    int g = lane >> 2, c = lane & 3;

    for (int idx = tid; idx < 128 * 32; idx += 256) {
        int n = idx >> 5, q4 = idx & 31;
        float4 v = *(const float4*)&Wp[n * D + q4 * 4];
        Wh[n][q4 * 2]     = pack_h2(v.x, v.y);
        Wh[n][q4 * 2 + 1] = pack_h2(v.z, v.w);
    }

    int sm_ = tid >> 1;
    int qb = (tid & 1) * 4;
    int gm = m0 + sm_;

    for (int ss = 0; ss < 2; ss++) {
        int set = p + ss * 2;
        const float* xp = (set == 0) ? x0 : (set == 1) ? x1 : (set == 2) ? x2 : x3;
        __half* h = g_h + (size_t)set * N * D;

        {
            float4 q[4];
#pragma unroll
            for (int r = 0; r < 4; r++) {
                q[r] = make_float4(0.f, 0.f, 0.f, 0.f);
                if (gm < N) q[r] = *(const float4*)&xp[(size_t)gm * D + (qb + r) * 4];
            }
#pragma unroll
            for (int r = 0; r < 4; r++) {
                Xh[0][sm_][(qb + r) * 2]     = pack_h2(q[r].x, q[r].y);
                Xh[0][sm_][(qb + r) * 2 + 1] = pack_h2(q[r].z, q[r].w);
            }
        }
        __syncthreads();

        float acc[4][4][4];
#pragma unroll
        for (int mi = 0; mi < 4; mi++)
#pragma unroll
            for (int ni = 0; ni < 4; ni++)
#pragma unroll
                for (int r = 0; r < 4; r++) acc[mi][ni][r] = 0.0f;

        for (int ck = 0; ck < NCHUNK; ck++) {
            int cur = ck & 1;
            float4 q[4];
            if (ck + 1 < NCHUNK) {
                int k0 = (ck + 1) * 32;
#pragma unroll
                for (int r = 0; r < 4; r++) {
                    q[r] = make_float4(0.f, 0.f, 0.f, 0.f);
                    if (gm < N) q[r] = *(const float4*)&xp[(size_t)gm * D + k0 + (qb + r) * 4];
                }
            }

#pragma unroll
            for (int ks2 = 0; ks2 < 2; ks2++) {
                int kofs = ks2 * 8;
                int wk = ck * 16 + kofs;
                uint32_t a[4][4], b[4][2];
#pragma unroll
                for (int mi = 0; mi < 4; mi++) {
                    int r = wm * 64 + mi * 16 + g;
                    a[mi][0] = Xh[cur][r][kofs + c];
                    a[mi][1] = Xh[cur][r + 8][kofs + c];
                    a[mi][2] = Xh[cur][r][kofs + c + 4];
                    a[mi][3] = Xh[cur][r + 8][kofs + c + 4];
                }
#pragma unroll
                for (int ni = 0; ni < 4; ni++) {
                    int n = wn * 32 + ni * 8 + g;
                    b[ni][0] = Wh[n][wk + c];
                    b[ni][1] = Wh[n][wk + c + 4];
                }
#pragma unroll
                for (int mi = 0; mi < 4; mi++)
#pragma unroll
                    for (int ni = 0; ni < 4; ni++)
                        mma_f16(acc[mi][ni], a[mi], b[ni]);
            }

            if (ck + 1 < NCHUNK) {
#pragma unroll
                for (int r = 0; r < 4; r++) {
                    Xh[1 - cur][sm_][(qb + r) * 2]     = pack_h2(q[r].x, q[r].y);
                    Xh[1 - cur][sm_][(qb + r) * 2 + 1] = pack_h2(q[r].z, q[r].w);
                }
            }
            __syncthreads();
        }

#pragma unroll
        for (int ni = 0; ni < 4; ni++) {
            int cb = wn * 32 + ni * 8 + 2 * c;
#pragma unroll
            for (int mi = 0; mi < 4; mi++) {
                int r0 = m0 + wm * 64 + mi * 16 + g;
                int r1 = r0 + 8;
                if (r0 < N)
                    *(__half2*)&h[(size_t)r0 * D + cb] =
                        __floats2half2_rn(acc[mi][ni][0], acc[mi][ni][1]);
                if (r1 < N)
                    *(__half2*)&h[(size_t)r1 * D + cb] =
                        __floats2half2_rn(acc[mi][ni][2], acc[mi][ni][3]);
            }
        }
    }
}

// ---------------------------------------------------------------------------
// Aggregation: out_s[i] = sum_j norm_ij * h_s[j]  + b_s   (fp32 accumulate)
__global__ void k_agg(const float* __restrict__ b1, const float* __restrict__ b2,
                      float* __restrict__ out, int N) {
    int gt = blockIdx.x * blockDim.x + threadIdx.x;
    int i = gt >> 5;
    int lane = gt & 31;
    if (i >= N) return;

    int pair = lane >> 4;
    int cp = lane & 15;
    int setA = pair * 2;
    int setB = setA + 1;

    const uint4* HA = (const uint4*)(g_h + (size_t)setA * N * D);
    const uint4* HB = (const uint4*)(g_h + (size_t)setB * N * D);

    float di = g_dis[i];
    float d2 = di * di;

    float accA[8], accB[8];
    {
        uint4 ua = HA[(size_t)i * 16 + cp];
        uint4 ub = HB[(size_t)i * 16 + cp];
        const half2* pa = (const half2*)&ua;
        const half2* pb = (const half2*)&ub;
#pragma unroll
        for (int q = 0; q < 4; q++) {
            float2 fa = __half22float2(pa[q]);
            float2 fb = __half22float2(pb[q]);
            accA[2 * q] = fa.x * d2; accA[2 * q + 1] = fa.y * d2;
            accB[2 * q] = fb.x * d2; accB[2 * q + 1] = fb.y * d2;
        }
    }

    int beg = g_off[i];
    int end = beg + g_deg[i];
    for (int j = beg; j < end; j++) {
        int s = g_src[j];
        float w = di * g_dis[s];
        uint4 ua = HA[(size_t)s * 16 + cp];
        uint4 ub = HB[(size_t)s * 16 + cp];
        const half2* pa = (const half2*)&ua;
        const half2* pb = (const half2*)&ub;
#pragma unroll
        for (int q = 0; q < 4; q++) {
            float2 fa = __half22float2(pa[q]);
            float2 fb = __half22float2(pb[q]);
            accA[2 * q]     = fmaf(fa.x, w, accA[2 * q]);
            accA[2 * q + 1] = fmaf(fa.y, w, accA[2 * q + 1]);
            accB[2 * q]     = fmaf(fb.x, w, accB[2 * q]);
            accB[2 * q + 1] = fmaf(fb.y, w, accB[2 * q + 1]);
        }
    }

    int col = cp * 8;
    float4 bA0 = *(const float4*)&b1[col];
    float4 bA1 = *(const float4*)&b1[col + 4];
    float4 bB0 = *(const float4*)&b2[col];
    float4 bB1 = *(const float4*)&b2[col + 4];

    float* oA = out + (size_t)setA * N * D + (size_t)i * D + col;
    float* oB = out + (size_t)setB * N * D + (size_t)i * D + col;
    *(float4*)oA       = make_float4(accA[0] + bA0.x, accA[1] + bA0.y,
                                     accA[2] + bA0.z, accA[3] + bA0.w);
    *(float4*)(oA + 4) = make_float4(accA[4] + bA1.x, accA[5] + bA1.y,
                                     accA[6] + bA1.z, accA[7] + bA1.w);
    *(float4*)oB       = make_float4(accB[0] + bB0.x, accB[1] + bB0.y,
                                     accB[2] + bB0.z, accB[3] + bB0.w);
    *(float4*)(oB + 4) = make_float4(accB[4] + bB1.x, accB[5] + bB1.y,
                                     accB[6] + bB1.z, accB[7] + bB1.w);
}

// ---------------------------------------------------------------------------
extern "C" void kernel_launch(void* const* d_in, const int* in_sizes, int n_in,
                              void* d_out, int out_size) {
    const float* x0 = (const float*)d_in[0];  // x_r1 (W1,b1)
    const float* x1 = (const float*)d_in[1];  // x_r2 (W2,b2)
    const float* x2 = (const float*)d_in[2];  // x_i1 (W1,b1)
    const float* x3 = (const float*)d_in[3];  // x_i2 (W2,b2)
    const void*  ei = d_in[4];                // edge_index: int64 OR int32
    const float* W1 = (const float*)d_in[5];
    const float* b1 = (const float*)d_in[6];
    const float* W2 = (const float*)d_in[7];
    const float* b2 = (const float*)d_in[8];
    float* out = (float*)d_out;

    int N = in_sizes[0] / D;
    int E = in_sizes[4] / 2;
    int nb_scan = (N + SCAN_B - 1) / SCAN_B;

    // common prefix on main stream
    k_detect_zero<<<(N + 255) / 256, 256>>>(ei, E, N);

    // fork: CSR chain on s2, GEMM on main stream
    cudaEventRecord(g_res.fork_ev, 0);
    cudaStreamWaitEvent(g_res.s2, g_res.fork_ev, 0);

    k_count<<<(E + 255) / 256, 256, 0, g_res.s2>>>(ei, E, N);
    k_scan_block<<<nb_scan, SCAN_B, 0, g_res.s2>>>(N, nb_scan);
    k_finalize<<<(N + 255) / 256, 256, 0, g_res.s2>>>(N);
    k_fill<<<(E + 255) / 256, 256, 0, g_res.s2>>>(ei, E, N);

    {
        dim3 grid((N + 127) / 128, 2);
        k_gemm<<<grid, 256>>>(x0, x1, x2, x3, W1, W2, N);
    }

    // join
    cudaEventRecord(g_res.join_ev, g_res.s2);
    cudaStreamWaitEvent(0, g_res.join_ev, 0);

    // aggregate fp16 h with fp32 accumulation, add bias, write out
    {
        long long threads = (long long)N * 32;
        int blocks = (int)((threads + 255) / 256);
        k_agg<<<blocks, 256>>>(b1, b2, out, N);
    }
}

// round 15
// speedup vs baseline: 1.1463x; 1.0580x over previous
#include <cuda_runtime.h>
#include <cuda_fp16.h>
#include <cstdint>

#define MAX_N 50000
#define MAX_E 800000
#define D 128
#define SCAN_B 512
#define MAX_BLK 128   // >= ceil(MAX_N/SCAN_B)

// Scratch (device globals: allocation forbidden in kernel_launch)
__device__ int    g_mode;             // 1 = edge_index is int64, 0 = int32
__device__ int    g_deg[MAX_N];       // edge in-degree (excl self-loop)
__device__ int    g_off[MAX_N];       // CSR row offsets
__device__ int    g_cur[MAX_N];       // fill cursors
__device__ int    g_bsum[MAX_BLK];    // scan block sums
__device__ int    g_scan_ctr;         // last-block ticket (zero-init, self-reset)
__device__ float  g_dis[MAX_N];       // rsqrt(deg+1)
__device__ int    g_src[MAX_E];       // CSR column indices (source nodes)
__device__ __half g_h[4ull * MAX_N * D];  // h = x @ W^T in fp16, per set

// Fork-join resources, created once at module load (host-side only)
struct StreamRes {
    cudaStream_t s2;
    cudaEvent_t  fork_ev, g0_ev, csr_ev, ax_ev;
    StreamRes() {
        cudaStreamCreateWithFlags(&s2, cudaStreamNonBlocking);
        cudaEventCreateWithFlags(&fork_ev, cudaEventDisableTiming);
        cudaEventCreateWithFlags(&g0_ev, cudaEventDisableTiming);
        cudaEventCreateWithFlags(&csr_ev, cudaEventDisableTiming);
        cudaEventCreateWithFlags(&ax_ev, cudaEventDisableTiming);
    }
};
static StreamRes g_res;

// ---------------------------------------------------------------------------
__global__ void k_detect_zero(const void* ei, int E, int N) {
    int i = blockIdx.x * blockDim.x + threadIdx.x;
    if (i < N) g_deg[i] = 0;
    if (i == 0) {
        const long long* p64 = (const long long*)ei;
        int n = E < 32 ? E : 32;
        int ok64 = 1;
        for (int k = 0; k < n; k++) {
            long long v = p64[k];
            if (v < 0 || v >= (long long)N) { ok64 = 0; break; }
        }
        g_mode = ok64;
    }
}

__device__ __forceinline__ int edge_at(const void* ei, long long idx, int mode) {
    if (mode) return (int)((const long long*)ei)[idx];
    return ((const int*)ei)[idx];
}

__global__ void k_count(const void* __restrict__ ei, int E, int N) {
    int e = blockIdx.x * blockDim.x + threadIdx.x;
    if (e >= E) return;
    int mode = g_mode;
    int d = edge_at(ei, (long long)E + e, mode);
    if (d >= 0 && d < N) atomicAdd(&g_deg[d], 1);
}

__global__ void k_scan_block(int N, int nb) {
    __shared__ int sm[SCAN_B];
    int i = blockIdx.x * SCAN_B + threadIdx.x;
    int v = (i < N) ? g_deg[i] : 0;
    sm[threadIdx.x] = v;
    __syncthreads();
#pragma unroll
    for (int o = 1; o < SCAN_B; o <<= 1) {
        int t = (threadIdx.x >= o) ? sm[threadIdx.x - o] : 0;
        __syncthreads();
        sm[threadIdx.x] += t;
        __syncthreads();
    }
    if (i < N) g_off[i] = sm[threadIdx.x] - v;
    if (threadIdx.x == SCAN_B - 1) g_bsum[blockIdx.x] = sm[SCAN_B - 1];
    __syncthreads();
    if (threadIdx.x == 0) {
        __threadfence();
        int t = atomicAdd(&g_scan_ctr, 1);
        if (t == nb - 1) {
            g_scan_ctr = 0;
            __threadfence();
            int acc = 0;
            for (int b = 0; b < nb; b++) { int s = g_bsum[b]; g_bsum[b] = acc; acc += s; }
        }
    }
}

__global__ void k_finalize(int N) {
    int i = blockIdx.x * blockDim.x + threadIdx.x;
    if (i < N) {
        int o = g_off[i] + g_bsum[i / SCAN_B];
        g_off[i] = o;
        g_cur[i] = o;
        g_dis[i] = rsqrtf((float)(g_deg[i] + 1));
    }
}

__global__ void k_fill(const void* __restrict__ ei, int E, int N) {
    int e = blockIdx.x * blockDim.x + threadIdx.x;
    if (e >= E) return;
    int mode = g_mode;
    int s = edge_at(ei, e, mode);
    int d = edge_at(ei, (long long)E + e, mode);
    if (s >= 0 && s < N && d >= 0 && d < N) {
        int pos = atomicAdd(&g_cur[d], 1);
        if (pos >= 0 && pos < E) g_src[pos] = s;
    }
}

// ---------------------------------------------------------------------------
// GEMM (no bias): sets {p, p+2} = fp16( x @ Wp^T )   (HMMA m16n8k16, f32 acc)
#define GP 68
#define XP 20
#define NCHUNK 4

__device__ __forceinline__ uint32_t pack_h2(float lo, float hi) {
    __half2 h = __floats2half2_rn(lo, hi);
    return *(uint32_t*)&h;
}

__device__ __forceinline__ void mma_f16(float* d, const uint32_t* a, const uint32_t* b) {
    asm volatile(
        "mma.sync.aligned.m16n8k16.row.col.f32.f16.f16.f32 "
        "{%0,%1,%2,%3}, {%4,%5,%6,%7}, {%8,%9}, {%0,%1,%2,%3};"
        : "+f"(d[0]), "+f"(d[1]), "+f"(d[2]), "+f"(d[3])
        : "r"(a[0]), "r"(a[1]), "r"(a[2]), "r"(a[3]), "r"(b[0]), "r"(b[1]));
}

__global__ void __launch_bounds__(256, 2) k_gemm(
        const float* __restrict__ xa, const float* __restrict__ xb,
        const float* __restrict__ W, int p, int N) {
    __shared__ uint32_t Wh[128][GP];
    __shared__ uint32_t Xh[2][128][XP];

    int tid = threadIdx.x;
    int m0 = blockIdx.x * 128;
    int warp = tid >> 5, lane = tid & 31;
    int wm = warp >> 2, wn = warp & 3;
    int g = lane >> 2, c = lane & 3;

    for (int idx = tid; idx < 128 * 32; idx += 256) {
        int n = idx >> 5, q4 = idx & 31;
        float4 v = *(const float4*)&W[n * D + q4 * 4];
        Wh[n][q4 * 2]     = pack_h2(v.x, v.y);
        Wh[n][q4 * 2 + 1] = pack_h2(v.z, v.w);
    }

    int sm_ = tid >> 1;
    int qb = (tid & 1) * 4;
    int gm = m0 + sm_;

    for (int ss = 0; ss < 2; ss++) {
        int set = p + ss * 2;
        const float* xp = ss ? xb : xa;
        __half* h = g_h + (size_t)set * N * D;

        {
            float4 q[4];
#pragma unroll
            for (int r = 0; r < 4; r++) {
                q[r] = make_float4(0.f, 0.f, 0.f, 0.f);
                if (gm < N) q[r] = *(const float4*)&xp[(size_t)gm * D + (qb + r) * 4];
            }
#pragma unroll
            for (int r = 0; r < 4; r++) {
                Xh[0][sm_][(qb + r) * 2]     = pack_h2(q[r].x, q[r].y);
                Xh[0][sm_][(qb + r) * 2 + 1] = pack_h2(q[r].z, q[r].w);
            }
        }
        __syncthreads();

        float acc[4][4][4];
#pragma unroll
        for (int mi = 0; mi < 4; mi++)
#pragma unroll
            for (int ni = 0; ni < 4; ni++)
#pragma unroll
                for (int r = 0; r < 4; r++) acc[mi][ni][r] = 0.0f;

        for (int ck = 0; ck < NCHUNK; ck++) {
            int cur = ck & 1;
            float4 q[4];
            if (ck + 1 < NCHUNK) {
                int k0 = (ck + 1) * 32;
#pragma unroll
                for (int r = 0; r < 4; r++) {
                    q[r] = make_float4(0.f, 0.f, 0.f, 0.f);
                    if (gm < N) q[r] = *(const float4*)&xp[(size_t)gm * D + k0 + (qb + r) * 4];
                }
            }

#pragma unroll
            for (int ks2 = 0; ks2 < 2; ks2++) {
                int kofs = ks2 * 8;
                int wk = ck * 16 + kofs;
                uint32_t a[4][4], b[4][2];
#pragma unroll
                for (int mi = 0; mi < 4; mi++) {
                    int r = wm * 64 + mi * 16 + g;
                    a[mi][0] = Xh[cur][r][kofs + c];
                    a[mi][1] = Xh[cur][r + 8][kofs + c];
                    a[mi][2] = Xh[cur][r][kofs + c + 4];
                    a[mi][3] = Xh[cur][r + 8][kofs + c + 4];
                }
#pragma unroll
                for (int ni = 0; ni < 4; ni++) {
                    int n = wn * 32 + ni * 8 + g;
                    b[ni][0] = Wh[n][wk + c];
                    b[ni][1] = Wh[n][wk + c + 4];
                }
#pragma unroll
                for (int mi = 0; mi < 4; mi++)
#pragma unroll
                    for (int ni = 0; ni < 4; ni++)
                        mma_f16(acc[mi][ni], a[mi], b[ni]);
            }

            if (ck + 1 < NCHUNK) {
#pragma unroll
                for (int r = 0; r < 4; r++) {
                    Xh[1 - cur][sm_][(qb + r) * 2]     = pack_h2(q[r].x, q[r].y);
                    Xh[1 - cur][sm_][(qb + r) * 2 + 1] = pack_h2(q[r].z, q[r].w);
                }
            }
            __syncthreads();
        }

#pragma unroll
        for (int ni = 0; ni < 4; ni++) {
            int cb = wn * 32 + ni * 8 + 2 * c;
#pragma unroll
            for (int mi = 0; mi < 4; mi++) {
                int r0 = m0 + wm * 64 + mi * 16 + g;
                int r1 = r0 + 8;
                if (r0 < N)
                    *(__half2*)&h[(size_t)r0 * D + cb] =
                        __floats2half2_rn(acc[mi][ni][0], acc[mi][ni][1]);
                if (r1 < N)
                    *(__half2*)&h[(size_t)r1 * D + cb] =
                        __floats2half2_rn(acc[mi][ni][2], acc[mi][ni][3]);
            }
        }
    }
}

// ---------------------------------------------------------------------------
// Group aggregation: two sets sharing one bias. One warp per node.
// Lanes 0-15 -> setA, lanes 16-31 -> setB; each lane owns one uint4 (8 cols).
__global__ void k_agg2(const float* __restrict__ bias, float* __restrict__ out,
                       int N, int setA, int setB) {
    int gt = blockIdx.x * blockDim.x + threadIdx.x;
    int i = gt >> 5;
    int lane = gt & 31;
    if (i >= N) return;

    int half = lane >> 4;
    int cp = lane & 15;
    int set = half ? setB : setA;

    const uint4* H = (const uint4*)(g_h + (size_t)set * N * D);

    float di = g_dis[i];
    float d2 = di * di;

    float acc[8];
    {
        uint4 u = H[(size_t)i * 16 + cp];
        const half2* ph = (const half2*)&u;
#pragma unroll
        for (int q = 0; q < 4; q++) {
            float2 f = __half22float2(ph[q]);
            acc[2 * q] = f.x * d2;
            acc[2 * q + 1] = f.y * d2;
        }
    }

    int beg = g_off[i];
    int end = beg + g_deg[i];
    for (int j = beg; j < end; j++) {
        int s = g_src[j];
        float w = di * g_dis[s];
        uint4 u = H[(size_t)s * 16 + cp];
        const half2* ph = (const half2*)&u;
#pragma unroll
        for (int q = 0; q < 4; q++) {
            float2 f = __half22float2(ph[q]);
            acc[2 * q]     = fmaf(f.x, w, acc[2 * q]);
            acc[2 * q + 1] = fmaf(f.y, w, acc[2 * q + 1]);
        }
    }

    int col = cp * 8;
    float4 bv0 = *(const float4*)&bias[col];
    float4 bv1 = *(const float4*)&bias[col + 4];

    float* o = out + (size_t)set * N * D + (size_t)i * D + col;
    *(float4*)o       = make_float4(acc[0] + bv0.x, acc[1] + bv0.y,
                                    acc[2] + bv0.z, acc[3] + bv0.w);
    *(float4*)(o + 4) = make_float4(acc[4] + bv1.x, acc[5] + bv1.y,
                                    acc[6] + bv1.z, acc[7] + bv1.w);
}

// ---------------------------------------------------------------------------
extern "C" void kernel_launch(void* const* d_in, const int* in_sizes, int n_in,
                              void* d_out, int out_size) {
    const float* x0 = (const float*)d_in[0];  // x_r1 (W1,b1)
    const float* x1 = (const float*)d_in[1];  // x_r2 (W2,b2)
    const float* x2 = (const float*)d_in[2];  // x_i1 (W1,b1)
    const float* x3 = (const float*)d_in[3];  // x_i2 (W2,b2)
    const void*  ei = d_in[4];                // edge_index: int64 OR int32
    const float* W1 = (const float*)d_in[5];
    const float* b1 = (const float*)d_in[6];
    const float* W2 = (const float*)d_in[7];
    const float* b2 = (const float*)d_in[8];
    float* out = (float*)d_out;

    int N = in_sizes[0] / D;
    int E = in_sizes[4] / 2;
    int nb_scan = (N + SCAN_B - 1) / SCAN_B;

    int agg_blocks = (int)(((long long)N * 32 + 255) / 256);
    dim3 ggrid((N + 127) / 128, 1);

    // common prefix on main stream
    k_detect_zero<<<(N + 255) / 256, 256>>>(ei, E, N);

    // fork: CSR chain on s2
    cudaEventRecord(g_res.fork_ev, 0);
    cudaStreamWaitEvent(g_res.s2, g_res.fork_ev, 0);

    k_count<<<(E + 255) / 256, 256, 0, g_res.s2>>>(ei, E, N);
    k_scan_block<<<nb_scan, SCAN_B, 0, g_res.s2>>>(N, nb_scan);
    k_finalize<<<(N + 255) / 256, 256, 0, g_res.s2>>>(N);
    k_fill<<<(E + 255) / 256, 256, 0, g_res.s2>>>(ei, E, N);
    cudaEventRecord(g_res.csr_ev, g_res.s2);

    // main: GEMM group X (sets 0,2 with W1), then group Y (sets 1,3 with W2)
    k_gemm<<<ggrid, 256>>>(x0, x2, W1, 0, N);
    cudaEventRecord(g_res.g0_ev, 0);
    k_gemm<<<ggrid, 256>>>(x1, x3, W2, 1, N);

    // s2: aggregate group X once CSR + GEMM0 are done (overlaps GEMM1 / agg_Y)
    cudaStreamWaitEvent(g_res.s2, g_res.g0_ev, 0);
    k_agg2<<<agg_blocks, 256, 0, g_res.s2>>>(b1, out, N, 0, 2);
    cudaEventRecord(g_res.ax_ev, g_res.s2);

    // main: aggregate group Y after GEMM1 (program order) + CSR (event)
    cudaStreamWaitEvent(0, g_res.csr_ev, 0);
    k_agg2<<<agg_blocks, 256>>>(b2, out, N, 1, 3);

    // join: graph end depends on agg_X as well
    cudaStreamWaitEvent(0, g_res.ax_ev, 0);
}

// round 16
// speedup vs baseline: 1.2047x; 1.0509x over previous
#include <cuda_runtime.h>
#include <cuda_fp16.h>
#include <cstdint>

#define MAX_N 50000
#define MAX_E 800000
#define D 128
#define SCAN_B 512
#define MAX_BLK 128   // >= ceil(MAX_N/SCAN_B)

// Scratch (device globals: allocation forbidden in kernel_launch)
__device__ int    g_mode;             // 1 = edge_index is int64, 0 = int32
__device__ int    g_deg[MAX_N];       // edge in-degree (excl self-loop)
__device__ int    g_off[MAX_N];       // CSR row offsets
__device__ int    g_cur[MAX_N];       // fill cursors
__device__ int    g_bsum[MAX_BLK];    // scan block sums
__device__ int    g_scan_ctr;         // last-block ticket (zero-init, self-reset)
__device__ float  g_dis[MAX_N];       // rsqrt(deg+1)
__device__ int    g_src[MAX_E];       // CSR column indices (source nodes)
__device__ __half g_h[4ull * MAX_N * D];  // h = x @ W^T in fp16, per set

// Fork-join resources, created once at module load (host-side only)
struct StreamRes {
    cudaStream_t s2, s3;
    cudaEvent_t  fork_ev, g0_ev, g1_ev, csr_ev, ax_ev;
    StreamRes() {
        cudaStreamCreateWithFlags(&s2, cudaStreamNonBlocking);
        cudaStreamCreateWithFlags(&s3, cudaStreamNonBlocking);
        cudaEventCreateWithFlags(&fork_ev, cudaEventDisableTiming);
        cudaEventCreateWithFlags(&g0_ev, cudaEventDisableTiming);
        cudaEventCreateWithFlags(&g1_ev, cudaEventDisableTiming);
        cudaEventCreateWithFlags(&csr_ev, cudaEventDisableTiming);
        cudaEventCreateWithFlags(&ax_ev, cudaEventDisableTiming);
    }
};
static StreamRes g_res;

// ---------------------------------------------------------------------------
__global__ void k_detect_zero(const void* ei, int E, int N) {
    int i = blockIdx.x * blockDim.x + threadIdx.x;
    if (i < N) g_deg[i] = 0;
    if (i == 0) {
        const long long* p64 = (const long long*)ei;
        int n = E < 32 ? E : 32;
        int ok64 = 1;
        for (int k = 0; k < n; k++) {
            long long v = p64[k];
            if (v < 0 || v >= (long long)N) { ok64 = 0; break; }
        }
        g_mode = ok64;
    }
}

__device__ __forceinline__ int edge_at(const void* ei, long long idx, int mode) {
    if (mode) return (int)((const long long*)ei)[idx];
    return ((const int*)ei)[idx];
}

__global__ void k_count(const void* __restrict__ ei, int E, int N) {
    int e = blockIdx.x * blockDim.x + threadIdx.x;
    if (e >= E) return;
    int mode = g_mode;
    int d = edge_at(ei, (long long)E + e, mode);
    if (d >= 0 && d < N) atomicAdd(&g_deg[d], 1);
}

__global__ void k_scan_block(int N, int nb) {
    __shared__ int sm[SCAN_B];
    int i = blockIdx.x * SCAN_B + threadIdx.x;
    int v = (i < N) ? g_deg[i] : 0;
    sm[threadIdx.x] = v;
    __syncthreads();
#pragma unroll
    for (int o = 1; o < SCAN_B; o <<= 1) {
        int t = (threadIdx.x >= o) ? sm[threadIdx.x - o] : 0;
        __syncthreads();
        sm[threadIdx.x] += t;
        __syncthreads();
    }
    if (i < N) g_off[i] = sm[threadIdx.x] - v;
    if (threadIdx.x == SCAN_B - 1) g_bsum[blockIdx.x] = sm[SCAN_B - 1];
    __syncthreads();
    if (threadIdx.x == 0) {
        __threadfence();
        int t = atomicAdd(&g_scan_ctr, 1);
        if (t == nb - 1) {
            g_scan_ctr = 0;
            __threadfence();
            int acc = 0;
            for (int b = 0; b < nb; b++) { int s = g_bsum[b]; g_bsum[b] = acc; acc += s; }
        }
    }
}

__global__ void k_finalize(int N) {
    int i = blockIdx.x * blockDim.x + threadIdx.x;
    if (i < N) {
        int o = g_off[i] + g_bsum[i / SCAN_B];
        g_off[i] = o;
        g_cur[i] = o;
        g_dis[i] = rsqrtf((float)(g_deg[i] + 1));
    }
}

__global__ void k_fill(const void* __restrict__ ei, int E, int N) {
    int e = blockIdx.x * blockDim.x + threadIdx.x;
    if (e >= E) return;
    int mode = g_mode;
    int s = edge_at(ei, e, mode);
    int d = edge_at(ei, (long long)E + e, mode);
    if (s >= 0 && s < N && d >= 0 && d < N) {
        int pos = atomicAdd(&g_cur[d], 1);
        if (pos >= 0 && pos < E) g_src[pos] = s;
    }
}

// ---------------------------------------------------------------------------
// GEMM (no bias): sets {p, p+2} = fp16( x @ Wp^T )   (HMMA m16n8k16, f32 acc)
#define GP 68
#define XP 20
#define NCHUNK 4

__device__ __forceinline__ uint32_t pack_h2(float lo, float hi) {
    __half2 h = __floats2half2_rn(lo, hi);
    return *(uint32_t*)&h;
}

__device__ __forceinline__ void mma_f16(float* d, const uint32_t* a, const uint32_t* b) {
    asm volatile(
        "mma.sync.aligned.m16n8k16.row.col.f32.f16.f16.f32 "
        "{%0,%1,%2,%3}, {%4,%5,%6,%7}, {%8,%9}, {%0,%1,%2,%3};"
        : "+f"(d[0]), "+f"(d[1]), "+f"(d[2]), "+f"(d[3])
        : "r"(a[0]), "r"(a[1]), "r"(a[2]), "r"(a[3]), "r"(b[0]), "r"(b[1]));
}

__global__ void __launch_bounds__(256, 2) k_gemm(
        const float* __restrict__ xa, const float* __restrict__ xb,
        const float* __restrict__ W, int p, int N) {
    __shared__ uint32_t Wh[128][GP];
    __shared__ uint32_t Xh[2][128][XP];

    int tid = threadIdx.x;
    int m0 = blockIdx.x * 128;
    int warp = tid >> 5, lane = tid & 31;
    int wm = warp >> 2, wn = warp & 3;
    int g = lane >> 2, c = lane & 3;

    for (int idx = tid; idx < 128 * 32; idx += 256) {
        int n = idx >> 5, q4 = idx & 31;
        float4 v = *(const float4*)&W[n * D + q4 * 4];
        Wh[n][q4 * 2]     = pack_h2(v.x, v.y);
        Wh[n][q4 * 2 + 1] = pack_h2(v.z, v.w);
    }

    int sm_ = tid >> 1;
    int qb = (tid & 1) * 4;
    int gm = m0 + sm_;

    for (int ss = 0; ss < 2; ss++) {
        int set = p + ss * 2;
        const float* xp = ss ? xb : xa;
        __half* h = g_h + (size_t)set * N * D;

        {
            float4 q[4];
#pragma unroll
            for (int r = 0; r < 4; r++) {
                q[r] = make_float4(0.f, 0.f, 0.f, 0.f);
                if (gm < N) q[r] = *(const float4*)&xp[(size_t)gm * D + (qb + r) * 4];
            }
#pragma unroll
            for (int r = 0; r < 4; r++) {
                Xh[0][sm_][(qb + r) * 2]     = pack_h2(q[r].x, q[r].y);
                Xh[0][sm_][(qb + r) * 2 + 1] = pack_h2(q[r].z, q[r].w);
            }
        }
        __syncthreads();

        float acc[4][4][4];
#pragma unroll
        for (int mi = 0; mi < 4; mi++)
#pragma unroll
            for (int ni = 0; ni < 4; ni++)
#pragma unroll
                for (int r = 0; r < 4; r++) acc[mi][ni][r] = 0.0f;

        for (int ck = 0; ck < NCHUNK; ck++) {
            int cur = ck & 1;
            float4 q[4];
            if (ck + 1 < NCHUNK) {
                int k0 = (ck + 1) * 32;
#pragma unroll
                for (int r = 0; r < 4; r++) {
                    q[r] = make_float4(0.f, 0.f, 0.f, 0.f);
                    if (gm < N) q[r] = *(const float4*)&xp[(size_t)gm * D + k0 + (qb + r) * 4];
                }
            }

#pragma unroll
            for (int ks2 = 0; ks2 < 2; ks2++) {
                int kofs = ks2 * 8;
                int wk = ck * 16 + kofs;
                uint32_t a[4][4], b[4][2];
#pragma unroll
                for (int mi = 0; mi < 4; mi++) {
                    int r = wm * 64 + mi * 16 + g;
                    a[mi][0] = Xh[cur][r][kofs + c];
                    a[mi][1] = Xh[cur][r + 8][kofs + c];
                    a[mi][2] = Xh[cur][r][kofs + c + 4];
                    a[mi][3] = Xh[cur][r + 8][kofs + c + 4];
                }
#pragma unroll
                for (int ni = 0; ni < 4; ni++) {
                    int n = wn * 32 + ni * 8 + g;
                    b[ni][0] = Wh[n][wk + c];
                    b[ni][1] = Wh[n][wk + c + 4];
                }
#pragma unroll
                for (int mi = 0; mi < 4; mi++)
#pragma unroll
                    for (int ni = 0; ni < 4; ni++)
                        mma_f16(acc[mi][ni], a[mi], b[ni]);
            }

            if (ck + 1 < NCHUNK) {
#pragma unroll
                for (int r = 0; r < 4; r++) {
                    Xh[1 - cur][sm_][(qb + r) * 2]     = pack_h2(q[r].x, q[r].y);
                    Xh[1 - cur][sm_][(qb + r) * 2 + 1] = pack_h2(q[r].z, q[r].w);
                }
            }
            __syncthreads();
        }

#pragma unroll
        for (int ni = 0; ni < 4; ni++) {
            int cb = wn * 32 + ni * 8 + 2 * c;
#pragma unroll
            for (int mi = 0; mi < 4; mi++) {
                int r0 = m0 + wm * 64 + mi * 16 + g;
                int r1 = r0 + 8;
                if (r0 < N)
                    *(__half2*)&h[(size_t)r0 * D + cb] =
                        __floats2half2_rn(acc[mi][ni][0], acc[mi][ni][1]);
                if (r1 < N)
                    *(__half2*)&h[(size_t)r1 * D + cb] =
                        __floats2half2_rn(acc[mi][ni][2], acc[mi][ni][3]);
            }
        }
    }
}

// ---------------------------------------------------------------------------
// Group aggregation: two sets sharing one bias. One warp per node.
// Lanes 0-15 -> setA, lanes 16-31 -> setB. Edge loop unrolled x2 for MLP.
__global__ void k_agg2(const float* __restrict__ bias, float* __restrict__ out,
                       int N, int setA, int setB) {
    int gt = blockIdx.x * blockDim.x + threadIdx.x;
    int i = gt >> 5;
    int lane = gt & 31;
    if (i >= N) return;

    int half = lane >> 4;
    int cp = lane & 15;
    int set = half ? setB : setA;

    const uint4* H = (const uint4*)(g_h + (size_t)set * N * D);

    float di = g_dis[i];
    float d2 = di * di;

    float acc[8];
    {
        uint4 u = H[(size_t)i * 16 + cp];
        const half2* ph = (const half2*)&u;
#pragma unroll
        for (int q = 0; q < 4; q++) {
            float2 f = __half22float2(ph[q]);
            acc[2 * q] = f.x * d2;
            acc[2 * q + 1] = f.y * d2;
        }
    }

    int beg = g_off[i];
    int end = beg + g_deg[i];
    int j = beg;
    for (; j + 1 < end; j += 2) {
        int s0 = g_src[j];
        int s1 = g_src[j + 1];
        float w0 = di * g_dis[s0];
        float w1 = di * g_dis[s1];
        uint4 u0 = H[(size_t)s0 * 16 + cp];
        uint4 u1 = H[(size_t)s1 * 16 + cp];
        const half2* p0 = (const half2*)&u0;
        const half2* p1 = (const half2*)&u1;
#pragma unroll
        for (int q = 0; q < 4; q++) {
            float2 f0 = __half22float2(p0[q]);
            float2 f1 = __half22float2(p1[q]);
            acc[2 * q]     = fmaf(f0.x, w0, acc[2 * q]);
            acc[2 * q + 1] = fmaf(f0.y, w0, acc[2 * q + 1]);
            acc[2 * q]     = fmaf(f1.x, w1, acc[2 * q]);
            acc[2 * q + 1] = fmaf(f1.y, w1, acc[2 * q + 1]);
        }
    }
    if (j < end) {
        int s = g_src[j];
        float w = di * g_dis[s];
        uint4 u = H[(size_t)s * 16 + cp];
        const half2* ph = (const half2*)&u;
#pragma unroll
        for (int q = 0; q < 4; q++) {
            float2 f = __half22float2(ph[q]);
            acc[2 * q]     = fmaf(f.x, w, acc[2 * q]);
            acc[2 * q + 1] = fmaf(f.y, w, acc[2 * q + 1]);
        }
    }

    int col = cp * 8;
    float4 bv0 = *(const float4*)&bias[col];
    float4 bv1 = *(const float4*)&bias[col + 4];

    float* o = out + (size_t)set * N * D + (size_t)i * D + col;
    *(float4*)o       = make_float4(acc[0] + bv0.x, acc[1] + bv0.y,
                                    acc[2] + bv0.z, acc[3] + bv0.w);
    *(float4*)(o + 4) = make_float4(acc[4] + bv1.x, acc[5] + bv1.y,
                                    acc[6] + bv1.z, acc[7] + bv1.w);
}

// ---------------------------------------------------------------------------
extern "C" void kernel_launch(void* const* d_in, const int* in_sizes, int n_in,
                              void* d_out, int out_size) {
    const float* x0 = (const float*)d_in[0];  // x_r1 (W1,b1)
    const float* x1 = (const float*)d_in[1];  // x_r2 (W2,b2)
    const float* x2 = (const float*)d_in[2];  // x_i1 (W1,b1)
    const float* x3 = (const float*)d_in[3];  // x_i2 (W2,b2)
    const void*  ei = d_in[4];                // edge_index: int64 OR int32
    const float* W1 = (const float*)d_in[5];
    const float* b1 = (const float*)d_in[6];
    const float* W2 = (const float*)d_in[7];
    const float* b2 = (const float*)d_in[8];
    float* out = (float*)d_out;

    int N = in_sizes[0] / D;
    int E = in_sizes[4] / 2;
    int nb_scan = (N + SCAN_B - 1) / SCAN_B;

    int agg_blocks = (int)(((long long)N * 32 + 255) / 256);
    dim3 ggrid((N + 127) / 128, 1);

    // common prefix on main stream
    k_detect_zero<<<(N + 255) / 256, 256>>>(ei, E, N);

    // fork: CSR chain on s2, GEMM1 on s3, GEMM0 on main (concurrent)
    cudaEventRecord(g_res.fork_ev, 0);
    cudaStreamWaitEvent(g_res.s2, g_res.fork_ev, 0);
    cudaStreamWaitEvent(g_res.s3, g_res.fork_ev, 0);

    k_count<<<(E + 255) / 256, 256, 0, g_res.s2>>>(ei, E, N);
    k_scan_block<<<nb_scan, SCAN_B, 0, g_res.s2>>>(N, nb_scan);
    k_finalize<<<(N + 255) / 256, 256, 0, g_res.s2>>>(N);
    k_fill<<<(E + 255) / 256, 256, 0, g_res.s2>>>(ei, E, N);
    cudaEventRecord(g_res.csr_ev, g_res.s2);

    k_gemm<<<ggrid, 256, 0, g_res.s3>>>(x1, x3, W2, 1, N);   // sets 1,3
    cudaEventRecord(g_res.g1_ev, g_res.s3);

    k_gemm<<<ggrid, 256>>>(x0, x2, W1, 0, N);                // sets 0,2
    cudaEventRecord(g_res.g0_ev, 0);

    // s2: aggregate group X (sets 0,2) after CSR (program order) + GEMM0
    cudaStreamWaitEvent(g_res.s2, g_res.g0_ev, 0);
    k_agg2<<<agg_blocks, 256, 0, g_res.s2>>>(b1, out, N, 0, 2);
    cudaEventRecord(g_res.ax_ev, g_res.s2);

    // main: aggregate group Y (sets 1,3) after GEMM1 + CSR
    cudaStreamWaitEvent(0, g_res.g1_ev, 0);
    cudaStreamWaitEvent(0, g_res.csr_ev, 0);
    k_agg2<<<agg_blocks, 256>>>(b2, out, N, 1, 3);

    // join
    cudaStreamWaitEvent(0, g_res.ax_ev, 0);
}